// round 12
// baseline (speedup 1.0000x reference)
#include <cuda_runtime.h>
#include <math.h>
#include <stdint.h>

#define BATCH   2
#define T_SEQ   2048
#define CDIM    1024
#define HEADS   16
#define DHEAD   64
#define C3      3072
#define MROWS   4096

__device__ float g_qkv[(size_t)MROWS * C3];   // 48 MB
__device__ float g_y  [(size_t)MROWS * CDIM]; // 16 MB

// ---- tf32 helpers ----------------------------------------------------------
__device__ __forceinline__ uint32_t f2tf32(float x) {
    uint32_t u; asm("cvt.rna.tf32.f32 %0, %1;" : "=r"(u) : "f"(x)); return u;
}
__device__ __forceinline__ void mma_tf32(float* d, const uint32_t* a, const uint32_t* b) {
    asm volatile("mma.sync.aligned.m16n8k8.row.col.f32.tf32.tf32.f32 "
        "{%0,%1,%2,%3}, {%4,%5,%6,%7}, {%8,%9}, {%0,%1,%2,%3};"
        : "+f"(d[0]), "+f"(d[1]), "+f"(d[2]), "+f"(d[3])
        : "r"(a[0]), "r"(a[1]), "r"(a[2]), "r"(a[3]), "r"(b[0]), "r"(b[1]));
}

// ---------------------------------------------------------------------------
// NT GEMM on tensor cores: C[M,N] = A[M,K] * B[N,K]^T via 3xTF32 mma.sync.
// Block 128x128, 256 thr, warp tile 64x32, BK=16, double-buffered panel SMEM.
// ONE barrier per chunk: compute(buf p) -> stage(buf 1-p) -> sync.
// ---------------------------------------------------------------------------
#define GS_PANEL 520
#define GS_A_HI  0
#define GS_A_LO  (4 * GS_PANEL)
#define GS_B_HI  (8 * GS_PANEL)
#define GS_B_LO  (12 * GS_PANEL)
#define GS_BUF   (16 * GS_PANEL)

__global__ void __launch_bounds__(256, 2)
gemm_tf32_kernel(const float* __restrict__ A,
                 const float* __restrict__ B,
                 float* __restrict__ C,
                 int M, int N, int K)
{
    extern __shared__ __align__(16) float gsm[];

    const int t    = threadIdx.x;
    const int lane = t & 31;
    const int w    = t >> 5;
    const int wm   = w >> 2;
    const int wn   = w & 3;
    const int grp  = lane >> 2;
    const int qt   = lane & 3;
    const int m0   = blockIdx.y * 128;
    const int n0   = blockIdx.x * 128;

    const int srow = t >> 2;
    const int sc4  = t & 3;

    float acc[4][4][4];
    #pragma unroll
    for (int mt = 0; mt < 4; mt++)
        #pragma unroll
        for (int nt = 0; nt < 4; nt++)
            #pragma unroll
            for (int i = 0; i < 4; i++) acc[mt][nt][i] = 0.f;

    const float* Ap0 = A + (size_t)(m0 + srow)      * K + sc4 * 4;
    const float* Ap1 = A + (size_t)(m0 + srow + 64) * K + sc4 * 4;
    const float* Bp0 = B + (size_t)(n0 + srow)      * K + sc4 * 4;
    const float* Bp1 = B + (size_t)(n0 + srow + 64) * K + sc4 * 4;

    auto stage = [&](float4 va0, float4 va1, float4 vb0, float4 vb1, int buf) {
        float* bb = gsm + buf * GS_BUF;
        const int off0 = sc4 * GS_PANEL + srow * 4;
        const int off1 = off0 + 256;
        float4 h, l;
        #define SPLIT_STORE(vec, hoff, loff)                                   \
            { uint32_t hx = f2tf32((vec).x), hy = f2tf32((vec).y),             \
                       hz = f2tf32((vec).z), hw = f2tf32((vec).w);             \
              h = make_float4(__uint_as_float(hx), __uint_as_float(hy),        \
                              __uint_as_float(hz), __uint_as_float(hw));       \
              l = make_float4(                                                  \
                  __uint_as_float(f2tf32((vec).x - __uint_as_float(hx))),      \
                  __uint_as_float(f2tf32((vec).y - __uint_as_float(hy))),      \
                  __uint_as_float(f2tf32((vec).z - __uint_as_float(hz))),      \
                  __uint_as_float(f2tf32((vec).w - __uint_as_float(hw))));     \
              *(float4*)&bb[hoff] = h; *(float4*)&bb[loff] = l; }
        SPLIT_STORE(va0, GS_A_HI + off0, GS_A_LO + off0);
        SPLIT_STORE(va1, GS_A_HI + off1, GS_A_LO + off1);
        SPLIT_STORE(vb0, GS_B_HI + off0, GS_B_LO + off0);
        SPLIT_STORE(vb1, GS_B_HI + off1, GS_B_LO + off1);
        #undef SPLIT_STORE
    };

    float4 va0 = *(const float4*)Ap0, va1 = *(const float4*)Ap1;
    float4 vb0 = *(const float4*)Bp0, vb1 = *(const float4*)Bp1;
    stage(va0, va1, vb0, vb1, 0);
    __syncthreads();

    const int abase = (wm * 64 + grp) * 4 + qt;
    const int bbase = (wn * 32 + grp) * 4 + qt;

    const int nch = K / 16;
    for (int ch = 0; ch < nch; ch++) {
        const bool has = (ch + 1 < nch);
        if (has) {
            va0 = *(const float4*)(Ap0 + (ch + 1) * 16);
            va1 = *(const float4*)(Ap1 + (ch + 1) * 16);
            vb0 = *(const float4*)(Bp0 + (ch + 1) * 16);
            vb1 = *(const float4*)(Bp1 + (ch + 1) * 16);
        }

        const float* Sb = gsm + (ch & 1) * GS_BUF;
        #pragma unroll
        for (int kg = 0; kg < 2; kg++) {
            const int pk = kg * 2 * GS_PANEL;
            uint32_t bh[4][2], bl[4][2];
            #pragma unroll
            for (int nt = 0; nt < 4; nt++) {
                const int o = pk + bbase + nt * 32;
                bh[nt][0] = __float_as_uint(Sb[GS_B_HI + o]);
                bh[nt][1] = __float_as_uint(Sb[GS_B_HI + o + GS_PANEL]);
                bl[nt][0] = __float_as_uint(Sb[GS_B_LO + o]);
                bl[nt][1] = __float_as_uint(Sb[GS_B_LO + o + GS_PANEL]);
            }
            #pragma unroll
            for (int mt = 0; mt < 4; mt++) {
                const int o = pk + abase + mt * 64;
                uint32_t ah[4], al[4];
                ah[0] = __float_as_uint(Sb[GS_A_HI + o]);
                ah[1] = __float_as_uint(Sb[GS_A_HI + o + 32]);
                ah[2] = __float_as_uint(Sb[GS_A_HI + o + GS_PANEL]);
                ah[3] = __float_as_uint(Sb[GS_A_HI + o + GS_PANEL + 32]);
                al[0] = __float_as_uint(Sb[GS_A_LO + o]);
                al[1] = __float_as_uint(Sb[GS_A_LO + o + 32]);
                al[2] = __float_as_uint(Sb[GS_A_LO + o + GS_PANEL]);
                al[3] = __float_as_uint(Sb[GS_A_LO + o + GS_PANEL + 32]);
                #pragma unroll
                for (int nt = 0; nt < 4; nt++) {
                    mma_tf32(acc[mt][nt], ah, bh[nt]);
                    mma_tf32(acc[mt][nt], al, bh[nt]);
                    mma_tf32(acc[mt][nt], ah, bl[nt]);
                }
            }
        }
        // single barrier per chunk: stage writes the OTHER buffer
        if (has) {
            stage(va0, va1, vb0, vb1, (ch + 1) & 1);
            __syncthreads();
        }
    }

    #pragma unroll
    for (int mt = 0; mt < 4; mt++) {
        #pragma unroll
        for (int nt = 0; nt < 4; nt++) {
            const int row = m0 + wm * 64 + mt * 16 + grp;
            const int col = n0 + wn * 32 + nt * 8 + qt * 2;
            *(float2*)&C[(size_t)row * N + col]       = make_float2(acc[mt][nt][0], acc[mt][nt][1]);
            *(float2*)&C[(size_t)(row + 8) * N + col] = make_float2(acc[mt][nt][2], acc[mt][nt][3]);
        }
    }
}

// ---------------------------------------------------------------------------
// Penalized attention. softmax(P - Z) == softmax(P[k] + prefix_excl_sigmoid).
// G=8 queries/warp (halves per-query K/V crossbar traffic vs G=4).
// Block: 8 warps x 8 queries = 64 queries, 64-key tiles.
//  - analytic softmax shift (no max reduce), pair-scan over permuted K rows
//  - 68.6 KB smem -> 3 CTAs/SM; reversed block order (longest first)
// smem: Ksh 64x68 (permuted) | Vsh 64x68 | qsh 64x68 | esh 8x8x64
// ---------------------------------------------------------------------------
#define ATTN_SMEM_FLOATS (4352 + 4352 + 4352 + 4096)

__global__ void __launch_bounds__(256, 3)
attn_kernel(const float* __restrict__ qkv, float* __restrict__ yout)
{
    extern __shared__ __align__(16) float sm[];
    float* Ksh = sm;                 // [64][68], permuted rows
    float* Vsh = sm + 4352;          // [64][68]
    float* qsh = sm + 8704;          // [64][68]
    float* esh = sm + 13056;         // [8][8][64]

    const int b     = blockIdx.z;
    const int h     = blockIdx.y;
    const int qbase = (int)(gridDim.x - 1 - blockIdx.x) * 64;  // longest first
    const int w     = threadIdx.x >> 5;
    const int lane  = threadIdx.x & 31;
    const int d0    = 2 * lane;
    const float scale = 0.125f;

    // load the block's 64 q vectors (64 rows x 16 float4)
    #pragma unroll
    for (int i = 0; i < 4; i++) {
        int idx = threadIdx.x + i * 256;
        int qr = idx >> 4, c4 = idx & 15;
        const float* qptr = qkv + (size_t)(b * T_SEQ + qbase + qr) * C3 + h * DHEAD + c4 * 4;
        *(float4*)&qsh[qr * 68 + c4 * 4] = *(const float4*)qptr;
    }

    const float* Kbase = qkv + (size_t)(b * T_SEQ) * C3 + CDIM     + h * DHEAD;
    const float* Vbase = qkv + (size_t)(b * T_SEQ) * C3 + 2 * CDIM + h * DHEAD;
    const int ntiles = (qbase >> 6) + 1;

    float denl[8], y0[8], y1[8];
    #pragma unroll
    for (int g = 0; g < 8; g++) { denl[g] = 0.f; y0[g] = 0.f; y1[g] = 0.f; }

    for (int tile = 0; tile < ntiles; tile++) {
        const int kt0 = tile << 6;
        __syncthreads();   // prev consumers done (covers qsh on tile 0)
        #pragma unroll
        for (int i = 0; i < 4; i++) {
            int idx = threadIdx.x + i * 256;
            int r = idx >> 4, c4 = idx & 15;
            size_t gofs = (size_t)(kt0 + r) * C3 + c4 * 4;
            int prow = (r & 1) ? (32 + (r >> 1)) : (r >> 1);
            *(float4*)&Ksh[prow * 68 + c4 * 4] = *(const float4*)&Kbase[gofs];
            *(float4*)&Vsh[r    * 68 + c4 * 4] = *(const float4*)&Vbase[gofs];
        }
        __syncthreads();

        // --- QK: lane owns keys kt0+2*lane, kt0+2*lane+1; 8 queries ---
        float p0[8], p1[8];
        #pragma unroll
        for (int g = 0; g < 8; g++) { p0[g] = 0.f; p1[g] = 0.f; }
        {
            const float4* K0 = (const float4*)&Ksh[lane * 68];
            const float4* K1 = (const float4*)&Ksh[(lane + 32) * 68];
            #pragma unroll
            for (int d4 = 0; d4 < 16; d4++) {
                float4 k0 = K0[d4], k1 = K1[d4];
                #pragma unroll
                for (int g = 0; g < 8; g++) {
                    float4 qv = *(const float4*)&qsh[(w * 8 + g) * 68 + d4 * 4];
                    p0[g] += qv.x * k0.x + qv.y * k0.y + qv.z * k0.z + qv.w * k0.w;
                    p1[g] += qv.x * k1.x + qv.y * k1.y + qv.z * k1.z + qv.w * k1.w;
                }
            }
        }

        // --- sigmoid pair-scan + shifted exp ---
        float alpha_g[8];
        #pragma unroll
        for (int g = 0; g < 8; g++) {
            const int q    = qbase + w * 8 + g;
            const int key0 = kt0 + 2 * lane;
            const bool v0 = (key0 <= q), v1 = (key0 + 1 <= q);
            const float P0 = p0[g] * scale;
            const float P1 = p1[g] * scale;
            const float s0 = v0 ? __fdividef(1.0f, 1.0f + __expf(-P0)) : 0.f;
            const float s1 = v1 ? __fdividef(1.0f, 1.0f + __expf(-P1)) : 0.f;

            float sp = s0 + s1;
            float sc = sp;
            #pragma unroll
            for (int off = 1; off < 32; off <<= 1) {
                float tv = __shfl_up_sync(0xffffffffu, sc, off);
                if (lane >= off) sc += tv;
            }
            const float tot  = __shfl_sync(0xffffffffu, sc, 31);
            const float excl = sc - sp;

            const float c0 = excl - tot - 8.0f;
            const float e0 = v0 ? __expf(P0 + c0)      : 0.f;
            const float e1 = v1 ? __expf(P1 + c0 + s0) : 0.f;
            const float al = __expf(-tot);
            denl[g] = denl[g] * al + e0 + e1;
            alpha_g[g] = al;
            *(float2*)&esh[(w * 8 + g) * 64 + 2 * lane] = make_float2(e0, e1);
        }
        __syncwarp();

        // --- AV: V tile read once per warp, reused across 8 queries ---
        #pragma unroll
        for (int g = 0; g < 8; g++) { y0[g] *= alpha_g[g]; y1[g] *= alpha_g[g]; }
        #pragma unroll
        for (int k4 = 0; k4 < 16; k4++) {
            float2 v0 = *(const float2*)&Vsh[(k4 * 4 + 0) * 68 + d0];
            float2 v1 = *(const float2*)&Vsh[(k4 * 4 + 1) * 68 + d0];
            float2 v2 = *(const float2*)&Vsh[(k4 * 4 + 2) * 68 + d0];
            float2 v3 = *(const float2*)&Vsh[(k4 * 4 + 3) * 68 + d0];
            #pragma unroll
            for (int g = 0; g < 8; g++) {
                float4 ev = *(const float4*)&esh[(w * 8 + g) * 64 + k4 * 4];
                y0[g] += ev.x * v0.x + ev.y * v1.x + ev.z * v2.x + ev.w * v3.x;
                y1[g] += ev.x * v0.y + ev.y * v1.y + ev.z * v2.y + ev.w * v3.y;
            }
        }
        __syncwarp();
    }

    #pragma unroll
    for (int g = 0; g < 8; g++) {
        float dsum = denl[g];
        #pragma unroll
        for (int off = 16; off; off >>= 1)
            dsum += __shfl_xor_sync(0xffffffffu, dsum, off);
        const float inv = 1.0f / dsum;
        const int q = qbase + w * 8 + g;
        float* yp = yout + (size_t)(b * T_SEQ + q) * CDIM + h * DHEAD + d0;
        *(float2*)yp = make_float2(y0[g] * inv, y1[g] * inv);
    }
}

// ---------------------------------------------------------------------------
extern "C" void kernel_launch(void* const* d_in, const int* in_sizes, int n_in,
                              void* d_out, int out_size)
{
    const float* x = nullptr; const float* Wa = nullptr; const float* Wp = nullptr;
    for (int i = 0; i < n_in; i++) {
        if (in_sizes[i] == BATCH * T_SEQ * CDIM)  x  = (const float*)d_in[i];
        else if (in_sizes[i] == C3 * CDIM)        Wa = (const float*)d_in[i];
        else if (in_sizes[i] == CDIM * CDIM)      Wp = (const float*)d_in[i];
    }
    float* out = (float*)d_out;

    void* qkv_p = nullptr; void* y_p = nullptr;
    cudaGetSymbolAddress(&qkv_p, g_qkv);
    cudaGetSymbolAddress(&y_p,   g_y);
    float* qkv = (float*)qkv_p;
    float* y   = (float*)y_p;

    const int GEMM_SMEM = 2 * GS_BUF * 4;         // 66,560 B
    const int ATTN_SMEM = ATTN_SMEM_FLOATS * 4;   // 68,608 B -> 3 CTAs/SM
    cudaFuncSetAttribute(gemm_tf32_kernel, cudaFuncAttributeMaxDynamicSharedMemorySize, GEMM_SMEM);
    cudaFuncSetAttribute(attn_kernel,      cudaFuncAttributeMaxDynamicSharedMemorySize, ATTN_SMEM);

    {   // qkv = x @ W_attn^T
        dim3 grid(C3 / 128, MROWS / 128);
        gemm_tf32_kernel<<<grid, 256, GEMM_SMEM>>>(x, Wa, qkv, MROWS, C3, CDIM);
    }
    {   // penalized attention
        dim3 grid(T_SEQ / 64, HEADS, BATCH);
        attn_kernel<<<grid, 256, ATTN_SMEM>>>(qkv, y);
    }
    {   // out = y @ W_proj^T
        dim3 grid(CDIM / 128, MROWS / 128);
        gemm_tf32_kernel<<<grid, 256, GEMM_SMEM>>>(y, Wp, out, MROWS, CDIM, CDIM);
    }
}

// round 13
// speedup vs baseline: 1.6506x; 1.6506x over previous
#include <cuda_runtime.h>
#include <math.h>
#include <stdint.h>

#define BATCH   2
#define T_SEQ   2048
#define CDIM    1024
#define HEADS   16
#define DHEAD   64
#define C3      3072
#define MROWS   4096

__device__ float g_qkv[(size_t)MROWS * C3];   // 48 MB
__device__ float g_y  [(size_t)MROWS * CDIM]; // 16 MB

// ---- tf32 helpers ----------------------------------------------------------
__device__ __forceinline__ uint32_t f2tf32(float x) {
    uint32_t u; asm("cvt.rna.tf32.f32 %0, %1;" : "=r"(u) : "f"(x)); return u;
}
__device__ __forceinline__ void mma_tf32(float* d, const uint32_t* a, const uint32_t* b) {
    asm volatile("mma.sync.aligned.m16n8k8.row.col.f32.tf32.tf32.f32 "
        "{%0,%1,%2,%3}, {%4,%5,%6,%7}, {%8,%9}, {%0,%1,%2,%3};"
        : "+f"(d[0]), "+f"(d[1]), "+f"(d[2]), "+f"(d[3])
        : "r"(a[0]), "r"(a[1]), "r"(a[2]), "r"(a[3]), "r"(b[0]), "r"(b[1]));
}

// ---------------------------------------------------------------------------
// NT GEMM on tensor cores (exact R11 version, measured 438us):
// C[M,N] = A[M,K] * B[N,K]^T via 3xTF32 mma.sync.
// Block 128x128, 256 thr, warp tile 64x32, BK=16, double-buffered panel SMEM,
// two barriers per chunk (compute -> sync -> stage -> sync).
// ---------------------------------------------------------------------------
#define GS_PANEL 520
#define GS_A_HI  0
#define GS_A_LO  (4 * GS_PANEL)
#define GS_B_HI  (8 * GS_PANEL)
#define GS_B_LO  (12 * GS_PANEL)
#define GS_BUF   (16 * GS_PANEL)

__global__ void __launch_bounds__(256, 2)
gemm_tf32_kernel(const float* __restrict__ A,
                 const float* __restrict__ B,
                 float* __restrict__ C,
                 int M, int N, int K)
{
    extern __shared__ __align__(16) float gsm[];

    const int t    = threadIdx.x;
    const int lane = t & 31;
    const int w    = t >> 5;
    const int wm   = w >> 2;
    const int wn   = w & 3;
    const int grp  = lane >> 2;
    const int qt   = lane & 3;
    const int m0   = blockIdx.y * 128;
    const int n0   = blockIdx.x * 128;

    const int srow = t >> 2;
    const int sc4  = t & 3;

    float acc[4][4][4];
    #pragma unroll
    for (int mt = 0; mt < 4; mt++)
        #pragma unroll
        for (int nt = 0; nt < 4; nt++)
            #pragma unroll
            for (int i = 0; i < 4; i++) acc[mt][nt][i] = 0.f;

    const float* Ap0 = A + (size_t)(m0 + srow)      * K + sc4 * 4;
    const float* Ap1 = A + (size_t)(m0 + srow + 64) * K + sc4 * 4;
    const float* Bp0 = B + (size_t)(n0 + srow)      * K + sc4 * 4;
    const float* Bp1 = B + (size_t)(n0 + srow + 64) * K + sc4 * 4;

    auto stage = [&](float4 va0, float4 va1, float4 vb0, float4 vb1, int buf) {
        float* bb = gsm + buf * GS_BUF;
        const int off0 = sc4 * GS_PANEL + srow * 4;
        const int off1 = off0 + 256;
        float4 h, l;
        #define SPLIT_STORE(vec, hoff, loff)                                   \
            { uint32_t hx = f2tf32((vec).x), hy = f2tf32((vec).y),             \
                       hz = f2tf32((vec).z), hw = f2tf32((vec).w);             \
              h = make_float4(__uint_as_float(hx), __uint_as_float(hy),        \
                              __uint_as_float(hz), __uint_as_float(hw));       \
              l = make_float4(                                                  \
                  __uint_as_float(f2tf32((vec).x - __uint_as_float(hx))),      \
                  __uint_as_float(f2tf32((vec).y - __uint_as_float(hy))),      \
                  __uint_as_float(f2tf32((vec).z - __uint_as_float(hz))),      \
                  __uint_as_float(f2tf32((vec).w - __uint_as_float(hw))));     \
              *(float4*)&bb[hoff] = h; *(float4*)&bb[loff] = l; }
        SPLIT_STORE(va0, GS_A_HI + off0, GS_A_LO + off0);
        SPLIT_STORE(va1, GS_A_HI + off1, GS_A_LO + off1);
        SPLIT_STORE(vb0, GS_B_HI + off0, GS_B_LO + off0);
        SPLIT_STORE(vb1, GS_B_HI + off1, GS_B_LO + off1);
        #undef SPLIT_STORE
    };

    float4 va0 = *(const float4*)Ap0, va1 = *(const float4*)Ap1;
    float4 vb0 = *(const float4*)Bp0, vb1 = *(const float4*)Bp1;
    stage(va0, va1, vb0, vb1, 0);
    __syncthreads();

    const int abase = (wm * 64 + grp) * 4 + qt;
    const int bbase = (wn * 32 + grp) * 4 + qt;

    const int nch = K / 16;
    for (int ch = 0; ch < nch; ch++) {
        const bool has = (ch + 1 < nch);
        if (has) {
            va0 = *(const float4*)(Ap0 + (ch + 1) * 16);
            va1 = *(const float4*)(Ap1 + (ch + 1) * 16);
            vb0 = *(const float4*)(Bp0 + (ch + 1) * 16);
            vb1 = *(const float4*)(Bp1 + (ch + 1) * 16);
        }

        const float* Sb = gsm + (ch & 1) * GS_BUF;
        #pragma unroll
        for (int kg = 0; kg < 2; kg++) {
            const int pk = kg * 2 * GS_PANEL;
            uint32_t bh[4][2], bl[4][2];
            #pragma unroll
            for (int nt = 0; nt < 4; nt++) {
                const int o = pk + bbase + nt * 32;
                bh[nt][0] = __float_as_uint(Sb[GS_B_HI + o]);
                bh[nt][1] = __float_as_uint(Sb[GS_B_HI + o + GS_PANEL]);
                bl[nt][0] = __float_as_uint(Sb[GS_B_LO + o]);
                bl[nt][1] = __float_as_uint(Sb[GS_B_LO + o + GS_PANEL]);
            }
            #pragma unroll
            for (int mt = 0; mt < 4; mt++) {
                const int o = pk + abase + mt * 64;
                uint32_t ah[4], al[4];
                ah[0] = __float_as_uint(Sb[GS_A_HI + o]);
                ah[1] = __float_as_uint(Sb[GS_A_HI + o + 32]);
                ah[2] = __float_as_uint(Sb[GS_A_HI + o + GS_PANEL]);
                ah[3] = __float_as_uint(Sb[GS_A_HI + o + GS_PANEL + 32]);
                al[0] = __float_as_uint(Sb[GS_A_LO + o]);
                al[1] = __float_as_uint(Sb[GS_A_LO + o + 32]);
                al[2] = __float_as_uint(Sb[GS_A_LO + o + GS_PANEL]);
                al[3] = __float_as_uint(Sb[GS_A_LO + o + GS_PANEL + 32]);
                #pragma unroll
                for (int nt = 0; nt < 4; nt++) {
                    mma_tf32(acc[mt][nt], ah, bh[nt]);
                    mma_tf32(acc[mt][nt], al, bh[nt]);
                    mma_tf32(acc[mt][nt], ah, bl[nt]);
                }
            }
        }
        __syncthreads();
        if (has) {
            stage(va0, va1, vb0, vb1, (ch + 1) & 1);
            __syncthreads();
        }
    }

    #pragma unroll
    for (int mt = 0; mt < 4; mt++) {
        #pragma unroll
        for (int nt = 0; nt < 4; nt++) {
            const int row = m0 + wm * 64 + mt * 16 + grp;
            const int col = n0 + wn * 32 + nt * 8 + qt * 2;
            *(float2*)&C[(size_t)row * N + col]       = make_float2(acc[mt][nt][0], acc[mt][nt][1]);
            *(float2*)&C[(size_t)(row + 8) * N + col] = make_float2(acc[mt][nt][2], acc[mt][nt][3]);
        }
    }
}

// ---------------------------------------------------------------------------
// Penalized attention. softmax(P - Z) == softmax(P[k] + prefix_excl_sigmoid).
// G=8 queries/warp (halves per-query K/V crossbar traffic vs G=4) at
// __launch_bounds__(256, 2): 128-reg cap -> NO SPILLS (the R12 failure was
// the 84-reg cap of occupancy-3 forcing local-memory spills).
// Block: 8 warps x 8 queries = 64 queries, 64-key tiles.
// smem: Ksh 64x68 (permuted) | Vsh 64x68 | qsh 64x68 | esh 8x8x64 = 68.6 KB
// ---------------------------------------------------------------------------
#define ATTN_SMEM_FLOATS (4352 + 4352 + 4352 + 4096)

__global__ void __launch_bounds__(256, 2)
attn_kernel(const float* __restrict__ qkv, float* __restrict__ yout)
{
    extern __shared__ __align__(16) float sm[];
    float* Ksh = sm;                 // [64][68], permuted rows
    float* Vsh = sm + 4352;          // [64][68]
    float* qsh = sm + 8704;          // [64][68]
    float* esh = sm + 13056;         // [8][8][64]

    const int b     = blockIdx.z;
    const int h     = blockIdx.y;
    const int qbase = (int)(gridDim.x - 1 - blockIdx.x) * 64;  // longest first
    const int w     = threadIdx.x >> 5;
    const int lane  = threadIdx.x & 31;
    const int d0    = 2 * lane;
    const float scale = 0.125f;

    // load the block's 64 q vectors
    #pragma unroll
    for (int i = 0; i < 4; i++) {
        int idx = threadIdx.x + i * 256;
        int qr = idx >> 4, c4 = idx & 15;
        const float* qptr = qkv + (size_t)(b * T_SEQ + qbase + qr) * C3 + h * DHEAD + c4 * 4;
        *(float4*)&qsh[qr * 68 + c4 * 4] = *(const float4*)qptr;
    }

    const float* Kbase = qkv + (size_t)(b * T_SEQ) * C3 + CDIM     + h * DHEAD;
    const float* Vbase = qkv + (size_t)(b * T_SEQ) * C3 + 2 * CDIM + h * DHEAD;
    const int ntiles = (qbase >> 6) + 1;

    float denl[8], y0[8], y1[8];
    #pragma unroll
    for (int g = 0; g < 8; g++) { denl[g] = 0.f; y0[g] = 0.f; y1[g] = 0.f; }

    for (int tile = 0; tile < ntiles; tile++) {
        const int kt0 = tile << 6;
        __syncthreads();
        #pragma unroll
        for (int i = 0; i < 4; i++) {
            int idx = threadIdx.x + i * 256;
            int r = idx >> 4, c4 = idx & 15;
            size_t gofs = (size_t)(kt0 + r) * C3 + c4 * 4;
            int prow = (r & 1) ? (32 + (r >> 1)) : (r >> 1);
            *(float4*)&Ksh[prow * 68 + c4 * 4] = *(const float4*)&Kbase[gofs];
            *(float4*)&Vsh[r    * 68 + c4 * 4] = *(const float4*)&Vbase[gofs];
        }
        __syncthreads();

        // --- QK: lane owns keys kt0+2*lane, kt0+2*lane+1; 8 queries ---
        float p0[8], p1[8];
        #pragma unroll
        for (int g = 0; g < 8; g++) { p0[g] = 0.f; p1[g] = 0.f; }
        {
            const float4* K0 = (const float4*)&Ksh[lane * 68];
            const float4* K1 = (const float4*)&Ksh[(lane + 32) * 68];
            #pragma unroll
            for (int d4 = 0; d4 < 16; d4++) {
                float4 k0 = K0[d4], k1 = K1[d4];
                #pragma unroll
                for (int g = 0; g < 8; g++) {
                    float4 qv = *(const float4*)&qsh[(w * 8 + g) * 68 + d4 * 4];
                    p0[g] += qv.x * k0.x + qv.y * k0.y + qv.z * k0.z + qv.w * k0.w;
                    p1[g] += qv.x * k1.x + qv.y * k1.y + qv.z * k1.z + qv.w * k1.w;
                }
            }
        }

        // --- sigmoid pair-scan + shifted exp ---
        float alpha_g[8];
        #pragma unroll
        for (int g = 0; g < 8; g++) {
            const int q    = qbase + w * 8 + g;
            const int key0 = kt0 + 2 * lane;
            const bool v0 = (key0 <= q), v1 = (key0 + 1 <= q);
            const float P0 = p0[g] * scale;
            const float P1 = p1[g] * scale;
            const float s0 = v0 ? __fdividef(1.0f, 1.0f + __expf(-P0)) : 0.f;
            const float s1 = v1 ? __fdividef(1.0f, 1.0f + __expf(-P1)) : 0.f;

            float sp = s0 + s1;
            float sc = sp;
            #pragma unroll
            for (int off = 1; off < 32; off <<= 1) {
                float tv = __shfl_up_sync(0xffffffffu, sc, off);
                if (lane >= off) sc += tv;
            }
            const float tot  = __shfl_sync(0xffffffffu, sc, 31);
            const float excl = sc - sp;

            const float c0 = excl - tot - 8.0f;
            const float e0 = v0 ? __expf(P0 + c0)      : 0.f;
            const float e1 = v1 ? __expf(P1 + c0 + s0) : 0.f;
            const float al = __expf(-tot);
            denl[g] = denl[g] * al + e0 + e1;
            alpha_g[g] = al;
            *(float2*)&esh[(w * 8 + g) * 64 + 2 * lane] = make_float2(e0, e1);
        }
        __syncwarp();

        // --- AV: V tile read once per warp, reused across 8 queries ---
        #pragma unroll
        for (int g = 0; g < 8; g++) { y0[g] *= alpha_g[g]; y1[g] *= alpha_g[g]; }
        #pragma unroll
        for (int k4 = 0; k4 < 16; k4++) {
            float2 v0 = *(const float2*)&Vsh[(k4 * 4 + 0) * 68 + d0];
            float2 v1 = *(const float2*)&Vsh[(k4 * 4 + 1) * 68 + d0];
            float2 v2 = *(const float2*)&Vsh[(k4 * 4 + 2) * 68 + d0];
            float2 v3 = *(const float2*)&Vsh[(k4 * 4 + 3) * 68 + d0];
            #pragma unroll
            for (int g = 0; g < 8; g++) {
                float4 ev = *(const float4*)&esh[(w * 8 + g) * 64 + k4 * 4];
                y0[g] += ev.x * v0.x + ev.y * v1.x + ev.z * v2.x + ev.w * v3.x;
                y1[g] += ev.x * v0.y + ev.y * v1.y + ev.z * v2.y + ev.w * v3.y;
            }
        }
        __syncwarp();
    }

    #pragma unroll
    for (int g = 0; g < 8; g++) {
        float dsum = denl[g];
        #pragma unroll
        for (int off = 16; off; off >>= 1)
            dsum += __shfl_xor_sync(0xffffffffu, dsum, off);
        const float inv = 1.0f / dsum;
        const int q = qbase + w * 8 + g;
        float* yp = yout + (size_t)(b * T_SEQ + q) * CDIM + h * DHEAD + d0;
        *(float2*)yp = make_float2(y0[g] * inv, y1[g] * inv);
    }
}

// ---------------------------------------------------------------------------
extern "C" void kernel_launch(void* const* d_in, const int* in_sizes, int n_in,
                              void* d_out, int out_size)
{
    const float* x = nullptr; const float* Wa = nullptr; const float* Wp = nullptr;
    for (int i = 0; i < n_in; i++) {
        if (in_sizes[i] == BATCH * T_SEQ * CDIM)  x  = (const float*)d_in[i];
        else if (in_sizes[i] == C3 * CDIM)        Wa = (const float*)d_in[i];
        else if (in_sizes[i] == CDIM * CDIM)      Wp = (const float*)d_in[i];
    }
    float* out = (float*)d_out;

    void* qkv_p = nullptr; void* y_p = nullptr;
    cudaGetSymbolAddress(&qkv_p, g_qkv);
    cudaGetSymbolAddress(&y_p,   g_y);
    float* qkv = (float*)qkv_p;
    float* y   = (float*)y_p;

    const int GEMM_SMEM = 2 * GS_BUF * 4;         // 66,560 B
    const int ATTN_SMEM = ATTN_SMEM_FLOATS * 4;   // 68,608 B -> 2 CTAs/SM
    cudaFuncSetAttribute(gemm_tf32_kernel, cudaFuncAttributeMaxDynamicSharedMemorySize, GEMM_SMEM);
    cudaFuncSetAttribute(attn_kernel,      cudaFuncAttributeMaxDynamicSharedMemorySize, ATTN_SMEM);

    {   // qkv = x @ W_attn^T
        dim3 grid(C3 / 128, MROWS / 128);
        gemm_tf32_kernel<<<grid, 256, GEMM_SMEM>>>(x, Wa, qkv, MROWS, C3, CDIM);
    }
    {   // penalized attention
        dim3 grid(T_SEQ / 64, HEADS, BATCH);
        attn_kernel<<<grid, 256, ATTN_SMEM>>>(qkv, y);
    }
    {   // out = y @ W_proj^T
        dim3 grid(CDIM / 128, MROWS / 128);
        gemm_tf32_kernel<<<grid, 256, GEMM_SMEM>>>(y, Wp, out, MROWS, CDIM, CDIM);
    }
}